// round 14
// baseline (speedup 1.0000x reference)
#include <cuda_runtime.h>
#include <cuda_fp16.h>
#include <cstdint>

// Problem dims
#define BB 2048   // batch
#define SS 128    // seq len
#define DD 512    // embedding dim
#define HH 2048   // hidden
#define CC 151    // classes

// All-fp16 pipeline (rel_err measured 1.9e-4, gate 1e-3).
#define NPAD2 256    // padded class rows for B2
#define SPLITK2 4    // K-split for GEMM2 (2048/4 = 512 per chunk)

// Scratch (device globals — allocation is forbidden)
__device__ __half g_A1[(size_t)BB * DD];                //  2 MB (plain fp16 avg)
__device__ __half g_B1[(size_t)HH * DD];                //  2 MB
__device__ __half g_A2[(size_t)BB * HH];                //  8 MB (plain fp16 h)
__device__ __half g_B2[(size_t)NPAD2 * HH];             //  1 MB
__device__ float  g_part[(size_t)SPLITK2 * BB * NPAD2]; //  8 MB

// ---------------------------------------------------------------------------
// helpers
// ---------------------------------------------------------------------------
__device__ __forceinline__ uint32_t smem_to_u32(const void* p) {
    uint32_t a;
    asm("{ .reg .u64 t; cvta.to.shared.u64 t, %1; cvt.u32.u64 %0, t; }" : "=r"(a) : "l"(p));
    return a;
}
__device__ __forceinline__ void cp_async16(uint32_t dst, const void* src) {
    asm volatile("cp.async.cg.shared.global [%0], [%1], 16;" :: "r"(dst), "l"(src) : "memory");
}
#define CP_ASYNC_COMMIT() asm volatile("cp.async.commit_group;" ::: "memory")
#define CP_ASYNC_WAIT0()  asm volatile("cp.async.wait_group 0;" ::: "memory")
#define CP_ASYNC_WAIT1()  asm volatile("cp.async.wait_group 1;" ::: "memory")

__device__ __forceinline__ void ldm_x4(uint32_t& r0, uint32_t& r1, uint32_t& r2, uint32_t& r3,
                                       uint32_t addr) {
    asm volatile("ldmatrix.sync.aligned.m8n8.x4.shared.b16 {%0,%1,%2,%3}, [%4];"
                 : "=r"(r0), "=r"(r1), "=r"(r2), "=r"(r3) : "r"(addr));
}
__device__ __forceinline__ void mma16816(float* c, const uint32_t* a, const uint32_t* b) {
    asm volatile(
        "mma.sync.aligned.m16n8k16.row.col.f32.f16.f16.f32 "
        "{%0,%1,%2,%3}, {%4,%5,%6,%7}, {%8,%9}, {%0,%1,%2,%3};"
        : "+f"(c[0]), "+f"(c[1]), "+f"(c[2]), "+f"(c[3])
        : "r"(a[0]), "r"(a[1]), "r"(a[2]), "r"(a[3]), "r"(b[0]), "r"(b[1]));
}
__device__ __forceinline__ uint32_t pack_h2(__half lo, __half hi) {
    return ((uint32_t)__half_as_ushort(hi) << 16) | (uint32_t)__half_as_ushort(lo);
}
// smem tile: rows x 64B (BK=32 fp16). 16B chunk c in row r lives at
// r*64 + (c ^ ((r>>1)&3))*16  -> conflict-free for ldmatrix 8-row reads.
__device__ __forceinline__ uint32_t sw_off(int r, int c) {
    return (uint32_t)(r * 64 + ((c ^ ((r >> 1) & 3)) << 4));
}

// ---------------------------------------------------------------------------
// Kernel 1: embedding gather + masked mean -> plain fp16 avg [BB][DD]
// Padding is a SUFFIX (reference: where(arange < length, ids, 0)), so the
// gather loop runs only to len = 1 + max{s: id[s]!=0}. Interior id==0 rows
// (random id drew 0) read the all-zero row and add exact zeros, while cnt
// counts only id!=0 — matching the reference mask semantics bit-for-bit.
// ---------------------------------------------------------------------------
__global__ __launch_bounds__(128)
void embed_avg_kernel(const int* __restrict__ ids,
                      const float4* __restrict__ emb) {
    int b = blockIdx.x;
    __shared__ int s_ids[SS];
    __shared__ int s_len;
    int tid = threadIdx.x;              // 0..127
    int myid = ids[b * SS + tid];
    s_ids[tid] = myid;
    if (tid == 0) s_len = 0;
    int cnt = __syncthreads_count(myid != 0);   // barrier (also covers s_len init)
    if (myid != 0) atomicMax(&s_len, tid + 1);
    __syncthreads();
    const int len = s_len;

    float4 acc = make_float4(0.f, 0.f, 0.f, 0.f);
    #pragma unroll 4
    for (int s = 0; s < len; ++s) {
        float4 v = emb[s_ids[s] * (DD / 4) + tid];
        acc.x += v.x; acc.y += v.y; acc.z += v.z; acc.w += v.w;
    }
    float inv = (cnt > 0) ? (1.0f / (float)cnt) : 0.0f;
    uint2 hp = make_uint2(
        pack_h2(__float2half(acc.x * inv), __float2half(acc.y * inv)),
        pack_h2(__float2half(acc.z * inv), __float2half(acc.w * inv)));
    *reinterpret_cast<uint2*>(&g_A1[(size_t)b * DD + tid * 4]) = hp;
}

// ---------------------------------------------------------------------------
// Transpose + convert: W [K][Nreal] f32 -> Bc [n][K] fp16 K-major.
// ---------------------------------------------------------------------------
__global__ void transconv_kernel(const float* __restrict__ W,
                                 __half* __restrict__ Bc,
                                 int K, int Nreal) {
    __shared__ float sm[32][33];
    int tx = threadIdx.x, ty = threadIdx.y;   // (32, 8)
    int n0 = blockIdx.x * 32, k0 = blockIdx.y * 32;

    #pragma unroll
    for (int r = 0; r < 4; r++) {
        int kk = k0 + ty + 8 * r;
        int nn = n0 + tx;
        sm[ty + 8 * r][tx] = (nn < Nreal) ? W[(size_t)kk * Nreal + nn] : 0.f;
    }
    __syncthreads();

    #pragma unroll
    for (int r = 0; r < 4; r++) {
        int nn = n0 + ty + 8 * r;
        int kk = k0 + tx;
        Bc[(size_t)nn * K + kk] = __float2half(sm[tx][ty + 8 * r]);
    }
}

// ---------------------------------------------------------------------------
// mma.sync fp16 GEMM, NT form: C[128x128] = A[128xKc] . B[128xKc]^T
// Both operands K-contiguous (row stride ld). BK=32, 3-stage cp.async
// pipeline, ONE __syncthreads per iteration.
// 8 warps: warp (wid>>2) -> 64-row half, (wid&3) -> 32-col quarter.
// MODE 0: v = relu(d + bias[n]); write plain fp16 h to outS (row stride HH).
// MODE 1: write raw f32 partial to outF[(z*BB+m)*NPAD2 + n].
// Dynamic smem: A stages 3 x 8 KB at [0,24K); B stages 3 x 8 KB at [24K,48K).
// ---------------------------------------------------------------------------
template <int MODE>
__global__ __launch_bounds__(256, 2)
void hmma_gemm_kernel(const __half* __restrict__ A,
                      const __half* __restrict__ Bm,
                      const float* __restrict__ bias,
                      __half* __restrict__ outS,
                      float* __restrict__ outF,
                      int ld, int kChunk) {
    extern __shared__ __align__(16) unsigned char smem_dyn[];
    const uint32_t sA = smem_to_u32(smem_dyn);            // 3 x 8192
    const uint32_t sB = sA + 3 * 8192;                    // 3 x 8192

    const int tid  = threadIdx.x;
    const int wid  = tid >> 5;
    const int lane = tid & 31;
    const int m0 = blockIdx.y * 128;
    const int n0 = blockIdx.x * 128;
    const int koff = blockIdx.z * kChunk;

    const __half* Ap = A + (size_t)m0 * ld + koff;
    const __half* Bp = Bm + (size_t)n0 * ld + koff;

    const int niter = kChunk / 32;

    // stage tile for iteration 'it' into stage buffer 'buf' (0..2)
    auto stage = [&](int it, int buf) {
        const __half* a_src = Ap + it * 32;
        const __half* b_src = Bp + it * 32;
        uint32_t dA = sA + buf * 8192;
        uint32_t dB = sB + buf * 8192;
        #pragma unroll
        for (int p = 0; p < 2; p++) {
            int i = p * 256 + tid;     // 0..511 : 16B chunks
            int r = i >> 2;            // row 0..127
            int c = i & 3;             // 16B chunk in row
            uint32_t off = sw_off(r, c);
            cp_async16(dA + off, a_src + (size_t)r * ld + c * 8);
            cp_async16(dB + off, b_src + (size_t)r * ld + c * 8);
        }
    };

    const int wm = (wid >> 2) * 64;
    const int wn = (wid & 3) * 32;

    float acc[4][4][4];
    #pragma unroll
    for (int i = 0; i < 4; i++)
        #pragma unroll
        for (int j = 0; j < 4; j++)
            #pragma unroll
            for (int q = 0; q < 4; q++) acc[i][j][q] = 0.f;

    // prologue: prefetch tiles 0 and 1
    stage(0, 0);
    CP_ASYNC_COMMIT();
    stage(1, 1);
    CP_ASYNC_COMMIT();

    for (int it = 0; it < niter; it++) {
        int buf = it % 3;
        CP_ASYNC_WAIT1();      // <=1 group pending -> stage(it) has landed
        __syncthreads();       // all warps past compute(it-1); buf (it-1)%3 free

        if (it + 2 < niter) {
            stage(it + 2, (it + 2) % 3);
            CP_ASYNC_COMMIT();
        }

        uint32_t aBase = sA + buf * 8192;
        uint32_t bBase = sB + buf * 8192;
        #pragma unroll
        for (int ks = 0; ks < 2; ks++) {
            uint32_t a[4][4];
            #pragma unroll
            for (int mi = 0; mi < 4; mi++) {
                int r = wm + mi * 16 + (lane & 15);
                int c = ks * 2 + (lane >> 4);
                ldm_x4(a[mi][0], a[mi][1], a[mi][2], a[mi][3], aBase + sw_off(r, c));
            }
            uint32_t b[4][2];
            #pragma unroll
            for (int nj = 0; nj < 2; nj++) {
                int r = wn + nj * 16 + (lane & 15);
                int c = ks * 2 + (lane >> 4);
                uint32_t r0, r1, r2, r3;
                ldm_x4(r0, r1, r2, r3, bBase + sw_off(r, c));
                b[nj * 2 + 0][0] = r0;  b[nj * 2 + 1][0] = r1;
                b[nj * 2 + 0][1] = r2;  b[nj * 2 + 1][1] = r3;
            }
            #pragma unroll
            for (int mi = 0; mi < 4; mi++)
                #pragma unroll
                for (int nj = 0; nj < 4; nj++)
                    mma16816(acc[mi][nj], a[mi], b[nj]);
        }
    }

    // Epilogue. acc frag (mi,nj): rows wm+mi*16 + (lane>>2) and +8;
    // cols wn+nj*8 + 2*(lane&3) + {0,1}.
    const int rr = lane >> 2;
    const int cpair = (lane & 3) * 2;
    #pragma unroll
    for (int mi = 0; mi < 4; mi++) {
        #pragma unroll
        for (int nj = 0; nj < 4; nj++) {
            int nl = wn + nj * 8 + cpair;          // local col (even)
            int n = n0 + nl;
            float b0 = 0.f, b1 = 0.f;
            if (MODE == 0) {
                b0 = __ldg(&bias[n]);
                b1 = __ldg(&bias[n + 1]);
            }
            #pragma unroll
            for (int h = 0; h < 2; h++) {          // h=0: row rr, h=1: row rr+8
                int m = m0 + wm + mi * 16 + rr + h * 8;
                float v0 = acc[mi][nj][2 * h + 0];
                float v1 = acc[mi][nj][2 * h + 1];
                if (MODE == 0) {
                    v0 = fmaxf(v0 + b0, 0.f);
                    v1 = fmaxf(v1 + b1, 0.f);
                    uint32_t hp = pack_h2(__float2half(v0), __float2half(v1));
                    *reinterpret_cast<uint32_t*>(&outS[(size_t)m * HH + n]) = hp;
                } else {
                    size_t zb = (size_t)blockIdx.z * BB;
                    *reinterpret_cast<float2*>(&outF[(zb + m) * NPAD2 + n]) =
                        make_float2(v0, v1);
                }
            }
        }
    }
}

// ---------------------------------------------------------------------------
// Reduce split-K partials: out[m][n] = b2[n] + sum_s part[s][m][n], n < CC
// ---------------------------------------------------------------------------
__global__ void reduce_k2_kernel(const float* __restrict__ part,
                                 const float* __restrict__ b2,
                                 float* __restrict__ out) {
    int m = blockIdx.x;
    int n = threadIdx.x;            // 160 threads
    if (n < CC) {
        float s = b2[n];
        #pragma unroll
        for (int z = 0; z < SPLITK2; z++)
            s += part[((size_t)z * BB + m) * NPAD2 + n];
        out[(size_t)m * CC + n] = s;
    }
}

// ---------------------------------------------------------------------------
// Launch. Inputs: ids i32[2048,128], emb f32[50000,512], W1 f32[512,2048],
// b1 f32[2048], W2 f32[2048,151], b2 f32[151]. Output f32[2048,151].
// ---------------------------------------------------------------------------
extern "C" void kernel_launch(void* const* d_in, const int* in_sizes, int n_in,
                              void* d_out, int out_size) {
    const int*    ids = (const int*)d_in[0];
    const float4* emb = (const float4*)d_in[1];
    const float*  W1  = (const float*)d_in[2];
    const float*  b1  = (const float*)d_in[3];
    const float*  W2  = (const float*)d_in[4];
    const float*  b2  = (const float*)d_in[5];
    float*        out = (float*)d_out;

    __half *A1, *B1, *A2, *B2;
    float* part;
    cudaGetSymbolAddress((void**)&A1, g_A1);
    cudaGetSymbolAddress((void**)&B1, g_B1);
    cudaGetSymbolAddress((void**)&A2, g_A2);
    cudaGetSymbolAddress((void**)&B2, g_B2);
    cudaGetSymbolAddress((void**)&part, g_part);

    const int SMEM_GEMM = 6 * 8192;   // 48 KB (3-stage A + B)
    static bool attr_done = false;
    if (!attr_done) {
        cudaFuncSetAttribute(hmma_gemm_kernel<0>,
                             cudaFuncAttributeMaxDynamicSharedMemorySize, SMEM_GEMM);
        cudaFuncSetAttribute(hmma_gemm_kernel<1>,
                             cudaFuncAttributeMaxDynamicSharedMemorySize, SMEM_GEMM);
        attr_done = true;
    }

    // 1) gather + masked mean -> plain fp16 avg (prefix-length bounded loop)
    embed_avg_kernel<<<BB, 128>>>(ids, emb);

    // 2) weight conversions (independent of (1))
    transconv_kernel<<<dim3(HH / 32, DD / 32), dim3(32, 8)>>>(W1, B1, DD, HH);
    transconv_kernel<<<dim3(NPAD2 / 32, HH / 32), dim3(32, 8)>>>(W2, B2, HH, CC);

    // 3) h = relu(A1 . B1^T + b1) -> plain fp16 A2   [2048 x 2048], K=512
    hmma_gemm_kernel<0><<<dim3(HH / 128, BB / 128, 1), 256, SMEM_GEMM>>>(
        A1, B1, b1, A2, nullptr, DD, DD);

    // 4) partials = A2 . B2^T over K chunks          [2048 x 256] x 4, K=512 each
    hmma_gemm_kernel<1><<<dim3(NPAD2 / 128, BB / 128, SPLITK2), 256, SMEM_GEMM>>>(
        A2, B2, nullptr, nullptr, part, HH, HH / SPLITK2);

    // 5) out = b2 + sum partials (n < 151)
    reduce_k2_kernel<<<BB, 160>>>(part, b2, out);
}

// round 15
// speedup vs baseline: 1.0264x; 1.0264x over previous
#include <cuda_runtime.h>
#include <cuda_fp16.h>
#include <cstdint>

// Problem dims
#define BB 2048   // batch
#define SS 128    // seq len
#define DD 512    // embedding dim
#define HH 2048   // hidden
#define CC 151    // classes

// All-fp16 pipeline (rel_err measured 1.9e-4, gate 1e-3).
#define NPAD2 256    // padded class rows for B2
#define SPLITK2 4    // K-split for GEMM2 (2048/4 = 512 per chunk)

// Scratch (device globals — allocation is forbidden)
__device__ __half g_A1[(size_t)BB * DD];                //  2 MB (plain fp16 avg)
__device__ __half g_B1[(size_t)HH * DD];                //  2 MB
__device__ __half g_A2[(size_t)BB * HH];                //  8 MB (plain fp16 h)
__device__ __half g_B2[(size_t)NPAD2 * HH];             //  1 MB
__device__ float  g_part[(size_t)SPLITK2 * BB * NPAD2]; //  8 MB

// ---------------------------------------------------------------------------
// helpers
// ---------------------------------------------------------------------------
__device__ __forceinline__ uint32_t smem_to_u32(const void* p) {
    uint32_t a;
    asm("{ .reg .u64 t; cvta.to.shared.u64 t, %1; cvt.u32.u64 %0, t; }" : "=r"(a) : "l"(p));
    return a;
}
__device__ __forceinline__ void cp_async16(uint32_t dst, const void* src) {
    asm volatile("cp.async.cg.shared.global [%0], [%1], 16;" :: "r"(dst), "l"(src) : "memory");
}
#define CP_ASYNC_COMMIT() asm volatile("cp.async.commit_group;" ::: "memory")
#define CP_ASYNC_WAIT0()  asm volatile("cp.async.wait_group 0;" ::: "memory")
#define CP_ASYNC_WAIT1()  asm volatile("cp.async.wait_group 1;" ::: "memory")

__device__ __forceinline__ void ldm_x4(uint32_t& r0, uint32_t& r1, uint32_t& r2, uint32_t& r3,
                                       uint32_t addr) {
    asm volatile("ldmatrix.sync.aligned.m8n8.x4.shared.b16 {%0,%1,%2,%3}, [%4];"
                 : "=r"(r0), "=r"(r1), "=r"(r2), "=r"(r3) : "r"(addr));
}
__device__ __forceinline__ void mma16816(float* c, const uint32_t* a, const uint32_t* b) {
    asm volatile(
        "mma.sync.aligned.m16n8k16.row.col.f32.f16.f16.f32 "
        "{%0,%1,%2,%3}, {%4,%5,%6,%7}, {%8,%9}, {%0,%1,%2,%3};"
        : "+f"(c[0]), "+f"(c[1]), "+f"(c[2]), "+f"(c[3])
        : "r"(a[0]), "r"(a[1]), "r"(a[2]), "r"(a[3]), "r"(b[0]), "r"(b[1]));
}
__device__ __forceinline__ uint32_t pack_h2(__half lo, __half hi) {
    return ((uint32_t)__half_as_ushort(hi) << 16) | (uint32_t)__half_as_ushort(lo);
}
// smem tile: rows x 64B (BK=32 fp16). 16B chunk c in row r lives at
// r*64 + (c ^ ((r>>1)&3))*16  -> conflict-free for ldmatrix 8-row reads.
__device__ __forceinline__ uint32_t sw_off(int r, int c) {
    return (uint32_t)(r * 64 + ((c ^ ((r >> 1) & 3)) << 4));
}

// ---------------------------------------------------------------------------
// Kernel 1: embedding gather + masked mean -> plain fp16 avg [BB][DD]
// Padding is a SUFFIX (reference: where(arange < length, ids, 0)). The loop
// runs to len16 = roundup16(1 + max{s: id[s]!=0}) with a FULLY UNROLLED
// 16-wide inner batch: compile-time inner bound keeps 16 LDG.128s
// front-batched (MLP~16) while skipping ~half the trips on average.
// Suffix entries of s_ids are 0 -> all-zero table row -> exact zero adds,
// so the sum is bit-identical to the full 128-trip version.
// ---------------------------------------------------------------------------
__global__ __launch_bounds__(128)
void embed_avg_kernel(const int* __restrict__ ids,
                      const float4* __restrict__ emb) {
    int b = blockIdx.x;
    __shared__ int s_ids[SS];
    __shared__ int s_len;
    int tid = threadIdx.x;              // 0..127
    int myid = ids[b * SS + tid];
    s_ids[tid] = myid;
    if (tid == 0) s_len = 0;
    int cnt = __syncthreads_count(myid != 0);   // barrier (also covers s_len init)
    if (myid != 0) atomicMax(&s_len, tid + 1);
    __syncthreads();
    const int len16 = (s_len + 15) & ~15;       // multiple of 16, <= 128

    float4 acc0 = make_float4(0.f, 0.f, 0.f, 0.f);
    float4 acc1 = make_float4(0.f, 0.f, 0.f, 0.f);
    for (int s0 = 0; s0 < len16; s0 += 16) {
        #pragma unroll
        for (int i = 0; i < 16; i += 2) {
            float4 v0 = emb[s_ids[s0 + i]     * (DD / 4) + tid];
            float4 v1 = emb[s_ids[s0 + i + 1] * (DD / 4) + tid];
            acc0.x += v0.x; acc0.y += v0.y; acc0.z += v0.z; acc0.w += v0.w;
            acc1.x += v1.x; acc1.y += v1.y; acc1.z += v1.z; acc1.w += v1.w;
        }
    }
    float inv = (cnt > 0) ? (1.0f / (float)cnt) : 0.0f;
    float vx = (acc0.x + acc1.x) * inv;
    float vy = (acc0.y + acc1.y) * inv;
    float vz = (acc0.z + acc1.z) * inv;
    float vw = (acc0.w + acc1.w) * inv;
    uint2 hp = make_uint2(
        pack_h2(__float2half(vx), __float2half(vy)),
        pack_h2(__float2half(vz), __float2half(vw)));
    *reinterpret_cast<uint2*>(&g_A1[(size_t)b * DD + tid * 4]) = hp;
}

// ---------------------------------------------------------------------------
// Transpose + convert: W [K][Nreal] f32 -> Bc [n][K] fp16 K-major.
// ---------------------------------------------------------------------------
__global__ void transconv_kernel(const float* __restrict__ W,
                                 __half* __restrict__ Bc,
                                 int K, int Nreal) {
    __shared__ float sm[32][33];
    int tx = threadIdx.x, ty = threadIdx.y;   // (32, 8)
    int n0 = blockIdx.x * 32, k0 = blockIdx.y * 32;

    #pragma unroll
    for (int r = 0; r < 4; r++) {
        int kk = k0 + ty + 8 * r;
        int nn = n0 + tx;
        sm[ty + 8 * r][tx] = (nn < Nreal) ? W[(size_t)kk * Nreal + nn] : 0.f;
    }
    __syncthreads();

    #pragma unroll
    for (int r = 0; r < 4; r++) {
        int nn = n0 + ty + 8 * r;
        int kk = k0 + tx;
        Bc[(size_t)nn * K + kk] = __float2half(sm[tx][ty + 8 * r]);
    }
}

// ---------------------------------------------------------------------------
// mma.sync fp16 GEMM, NT form: C[128x128] = A[128xKc] . B[128xKc]^T
// Both operands K-contiguous (row stride ld). BK=32, 3-stage cp.async
// pipeline, ONE __syncthreads per iteration.
// 8 warps: warp (wid>>2) -> 64-row half, (wid&3) -> 32-col quarter.
// MODE 0: v = relu(d + bias[n]); write plain fp16 h to outS (row stride HH).
// MODE 1: write raw f32 partial to outF[(z*BB+m)*NPAD2 + n].
// Dynamic smem: A stages 3 x 8 KB at [0,24K); B stages 3 x 8 KB at [24K,48K).
// ---------------------------------------------------------------------------
template <int MODE>
__global__ __launch_bounds__(256, 2)
void hmma_gemm_kernel(const __half* __restrict__ A,
                      const __half* __restrict__ Bm,
                      const float* __restrict__ bias,
                      __half* __restrict__ outS,
                      float* __restrict__ outF,
                      int ld, int kChunk) {
    extern __shared__ __align__(16) unsigned char smem_dyn[];
    const uint32_t sA = smem_to_u32(smem_dyn);            // 3 x 8192
    const uint32_t sB = sA + 3 * 8192;                    // 3 x 8192

    const int tid  = threadIdx.x;
    const int wid  = tid >> 5;
    const int lane = tid & 31;
    const int m0 = blockIdx.y * 128;
    const int n0 = blockIdx.x * 128;
    const int koff = blockIdx.z * kChunk;

    const __half* Ap = A + (size_t)m0 * ld + koff;
    const __half* Bp = Bm + (size_t)n0 * ld + koff;

    const int niter = kChunk / 32;

    // stage tile for iteration 'it' into stage buffer 'buf' (0..2)
    auto stage = [&](int it, int buf) {
        const __half* a_src = Ap + it * 32;
        const __half* b_src = Bp + it * 32;
        uint32_t dA = sA + buf * 8192;
        uint32_t dB = sB + buf * 8192;
        #pragma unroll
        for (int p = 0; p < 2; p++) {
            int i = p * 256 + tid;     // 0..511 : 16B chunks
            int r = i >> 2;            // row 0..127
            int c = i & 3;             // 16B chunk in row
            uint32_t off = sw_off(r, c);
            cp_async16(dA + off, a_src + (size_t)r * ld + c * 8);
            cp_async16(dB + off, b_src + (size_t)r * ld + c * 8);
        }
    };

    const int wm = (wid >> 2) * 64;
    const int wn = (wid & 3) * 32;

    float acc[4][4][4];
    #pragma unroll
    for (int i = 0; i < 4; i++)
        #pragma unroll
        for (int j = 0; j < 4; j++)
            #pragma unroll
            for (int q = 0; q < 4; q++) acc[i][j][q] = 0.f;

    // prologue: prefetch tiles 0 and 1
    stage(0, 0);
    CP_ASYNC_COMMIT();
    stage(1, 1);
    CP_ASYNC_COMMIT();

    for (int it = 0; it < niter; it++) {
        int buf = it % 3;
        CP_ASYNC_WAIT1();      // <=1 group pending -> stage(it) has landed
        __syncthreads();       // all warps past compute(it-1); buf (it-1)%3 free

        if (it + 2 < niter) {
            stage(it + 2, (it + 2) % 3);
            CP_ASYNC_COMMIT();
        }

        uint32_t aBase = sA + buf * 8192;
        uint32_t bBase = sB + buf * 8192;
        #pragma unroll
        for (int ks = 0; ks < 2; ks++) {
            uint32_t a[4][4];
            #pragma unroll
            for (int mi = 0; mi < 4; mi++) {
                int r = wm + mi * 16 + (lane & 15);
                int c = ks * 2 + (lane >> 4);
                ldm_x4(a[mi][0], a[mi][1], a[mi][2], a[mi][3], aBase + sw_off(r, c));
            }
            uint32_t b[4][2];
            #pragma unroll
            for (int nj = 0; nj < 2; nj++) {
                int r = wn + nj * 16 + (lane & 15);
                int c = ks * 2 + (lane >> 4);
                uint32_t r0, r1, r2, r3;
                ldm_x4(r0, r1, r2, r3, bBase + sw_off(r, c));
                b[nj * 2 + 0][0] = r0;  b[nj * 2 + 1][0] = r1;
                b[nj * 2 + 0][1] = r2;  b[nj * 2 + 1][1] = r3;
            }
            #pragma unroll
            for (int mi = 0; mi < 4; mi++)
                #pragma unroll
                for (int nj = 0; nj < 4; nj++)
                    mma16816(acc[mi][nj], a[mi], b[nj]);
        }
    }

    // Epilogue. acc frag (mi,nj): rows wm+mi*16 + (lane>>2) and +8;
    // cols wn+nj*8 + 2*(lane&3) + {0,1}.
    const int rr = lane >> 2;
    const int cpair = (lane & 3) * 2;
    #pragma unroll
    for (int mi = 0; mi < 4; mi++) {
        #pragma unroll
        for (int nj = 0; nj < 4; nj++) {
            int nl = wn + nj * 8 + cpair;          // local col (even)
            int n = n0 + nl;
            float b0 = 0.f, b1 = 0.f;
            if (MODE == 0) {
                b0 = __ldg(&bias[n]);
                b1 = __ldg(&bias[n + 1]);
            }
            #pragma unroll
            for (int h = 0; h < 2; h++) {          // h=0: row rr, h=1: row rr+8
                int m = m0 + wm + mi * 16 + rr + h * 8;
                float v0 = acc[mi][nj][2 * h + 0];
                float v1 = acc[mi][nj][2 * h + 1];
                if (MODE == 0) {
                    v0 = fmaxf(v0 + b0, 0.f);
                    v1 = fmaxf(v1 + b1, 0.f);
                    uint32_t hp = pack_h2(__float2half(v0), __float2half(v1));
                    *reinterpret_cast<uint32_t*>(&outS[(size_t)m * HH + n]) = hp;
                } else {
                    size_t zb = (size_t)blockIdx.z * BB;
                    *reinterpret_cast<float2*>(&outF[(zb + m) * NPAD2 + n]) =
                        make_float2(v0, v1);
                }
            }
        }
    }
}

// ---------------------------------------------------------------------------
// Reduce split-K partials: out[m][n] = b2[n] + sum_s part[s][m][n], n < CC
// ---------------------------------------------------------------------------
__global__ void reduce_k2_kernel(const float* __restrict__ part,
                                 const float* __restrict__ b2,
                                 float* __restrict__ out) {
    int m = blockIdx.x;
    int n = threadIdx.x;            // 160 threads
    if (n < CC) {
        float s = b2[n];
        #pragma unroll
        for (int z = 0; z < SPLITK2; z++)
            s += part[((size_t)z * BB + m) * NPAD2 + n];
        out[(size_t)m * CC + n] = s;
    }
}

// ---------------------------------------------------------------------------
// Launch. Inputs: ids i32[2048,128], emb f32[50000,512], W1 f32[512,2048],
// b1 f32[2048], W2 f32[2048,151], b2 f32[151]. Output f32[2048,151].
// ---------------------------------------------------------------------------
extern "C" void kernel_launch(void* const* d_in, const int* in_sizes, int n_in,
                              void* d_out, int out_size) {
    const int*    ids = (const int*)d_in[0];
    const float4* emb = (const float4*)d_in[1];
    const float*  W1  = (const float*)d_in[2];
    const float*  b1  = (const float*)d_in[3];
    const float*  W2  = (const float*)d_in[4];
    const float*  b2  = (const float*)d_in[5];
    float*        out = (float*)d_out;

    __half *A1, *B1, *A2, *B2;
    float* part;
    cudaGetSymbolAddress((void**)&A1, g_A1);
    cudaGetSymbolAddress((void**)&B1, g_B1);
    cudaGetSymbolAddress((void**)&A2, g_A2);
    cudaGetSymbolAddress((void**)&B2, g_B2);
    cudaGetSymbolAddress((void**)&part, g_part);

    const int SMEM_GEMM = 6 * 8192;   // 48 KB (3-stage A + B)
    static bool attr_done = false;
    if (!attr_done) {
        cudaFuncSetAttribute(hmma_gemm_kernel<0>,
                             cudaFuncAttributeMaxDynamicSharedMemorySize, SMEM_GEMM);
        cudaFuncSetAttribute(hmma_gemm_kernel<1>,
                             cudaFuncAttributeMaxDynamicSharedMemorySize, SMEM_GEMM);
        attr_done = true;
    }

    // 1) gather + masked mean -> plain fp16 avg (len16-bounded, 16-wide batches)
    embed_avg_kernel<<<BB, 128>>>(ids, emb);

    // 2) weight conversions (independent of (1))
    transconv_kernel<<<dim3(HH / 32, DD / 32), dim3(32, 8)>>>(W1, B1, DD, HH);
    transconv_kernel<<<dim3(NPAD2 / 32, HH / 32), dim3(32, 8)>>>(W2, B2, HH, CC);

    // 3) h = relu(A1 . B1^T + b1) -> plain fp16 A2   [2048 x 2048], K=512
    hmma_gemm_kernel<0><<<dim3(HH / 128, BB / 128, 1), 256, SMEM_GEMM>>>(
        A1, B1, b1, A2, nullptr, DD, DD);

    // 4) partials = A2 . B2^T over K chunks          [2048 x 256] x 4, K=512 each
    hmma_gemm_kernel<1><<<dim3(NPAD2 / 128, BB / 128, SPLITK2), 256, SMEM_GEMM>>>(
        A2, B2, nullptr, nullptr, part, HH, HH / SPLITK2);

    // 5) out = b2 + sum partials (n < 151)
    reduce_k2_kernel<<<BB, 160>>>(part, b2, out);
}